// round 14
// baseline (speedup 1.0000x reference)
#include <cuda_runtime.h>
#include <cuda_bf16.h>
#include <math.h>
#include <stdint.h>

#define L_SEQ   2048
#define BATCH   2
#define NHEADS  16
#define HD      64
#define DMODEL  1024
#define MROWS   (BATCH * L_SEQ)   // 4096
#define BHL     (BATCH * NHEADS * L_SEQ * HD)
#define AM      (MROWS * DMODEL)
#define WM      (DMODEL * DMODEL)

// Scratch (__device__ globals allowed)
__device__ __nv_bfloat16 g_Ih[3 * AM], g_Il[3 * AM];   // split query/key/value
__device__ __nv_bfloat16 g_Wh[4 * WM], g_Wl[4 * WM];   // split Wq,Wk,Wv,Wo
__device__ __nv_bfloat16 g_Qhi[BHL], g_Qlo[BHL];       // [B,H,L,64], scaled 0.125
__device__ __nv_bfloat16 g_Khi[BHL], g_Klo[BHL];
__device__ __nv_bfloat16 g_Vhi[BHL], g_Vlo[BHL];
__device__ __nv_bfloat16 g_Ohi[AM], g_Olo[AM];         // attn out, [B,L,D] hi/lo

// ===========================================================================
// helpers (baseline PTX: ldmatrix sm_75+, mma.bf16 sm_80+, cp.async sm_80+)
// ===========================================================================
__device__ __forceinline__ uint32_t smem_u32(const void* p) {
    return (uint32_t)__cvta_generic_to_shared(p);
}
#define SWZ(off) (((uint32_t)(off)) ^ ((((uint32_t)(off)) >> 3) & 0x70))

__device__ __forceinline__ void cp16(uint32_t dst, const void* src) {
    asm volatile("cp.async.ca.shared.global [%0], [%1], 16;"
                 :: "r"(dst), "l"(src) : "memory");
}
#define CP_COMMIT() asm volatile("cp.async.commit_group;" ::: "memory")
#define CP_WAIT0()  asm volatile("cp.async.wait_group 0;" ::: "memory")
#define CP_WAIT1()  asm volatile("cp.async.wait_group 1;" ::: "memory")

__device__ __forceinline__ void ldm_x4(uint32_t* r, uint32_t addr) {
    asm volatile("ldmatrix.sync.aligned.m8n8.x4.shared.b16 {%0,%1,%2,%3}, [%4];"
                 : "=r"(r[0]), "=r"(r[1]), "=r"(r[2]), "=r"(r[3]) : "r"(addr));
}
__device__ __forceinline__ void ldm_x4_t(uint32_t* r, uint32_t addr) {
    asm volatile("ldmatrix.sync.aligned.m8n8.x4.trans.shared.b16 {%0,%1,%2,%3}, [%4];"
                 : "=r"(r[0]), "=r"(r[1]), "=r"(r[2]), "=r"(r[3]) : "r"(addr));
}
__device__ __forceinline__ void mma_bf16(float* d, const uint32_t* a, const uint32_t* b) {
    asm volatile("mma.sync.aligned.m16n8k16.row.col.f32.bf16.bf16.f32 "
                 "{%0,%1,%2,%3}, {%4,%5,%6,%7}, {%8,%9}, {%0,%1,%2,%3};"
                 : "+f"(d[0]), "+f"(d[1]), "+f"(d[2]), "+f"(d[3])
                 : "r"(a[0]), "r"(a[1]), "r"(a[2]), "r"(a[3]),
                   "r"(b[0]), "r"(b[1]));
}
__device__ __forceinline__ uint32_t pack_hi(float a, float b) {
    return __byte_perm(__float_as_uint(a), __float_as_uint(b), 0x7632);
}
__device__ __forceinline__ uint32_t pack_lo(float a, float b) {
    float ra = a - __uint_as_float(__float_as_uint(a) & 0xffff0000u);
    float rb = b - __uint_as_float(__float_as_uint(b) & 0xffff0000u);
    uint32_t r;
    asm("cvt.rn.satfinite.bf16x2.f32 %0, %1, %2;" : "=r"(r) : "f"(rb), "f"(ra));
    return r;
}

// ===========================================================================
// batched fp32 -> bf16 hi/lo split kernels
// ===========================================================================
__device__ __forceinline__ void split_one(const float4* src, uint2* hi, uint2* lo, int i) {
    float4 v = src[i];
    uint2 h, l;
    h.x = pack_hi(v.x, v.y);  h.y = pack_hi(v.z, v.w);
    l.x = pack_lo(v.x, v.y);  l.y = pack_lo(v.z, v.w);
    hi[i] = h;  lo[i] = l;
}

__global__ void split_in3(const float4* __restrict__ q, const float4* __restrict__ k,
                          const float4* __restrict__ v,
                          uint2* __restrict__ hi, uint2* __restrict__ lo)
{
    int i = blockIdx.x * blockDim.x + threadIdx.x;
    int z = blockIdx.y;
    const float4* src = (z == 0) ? q : (z == 1) ? k : v;
    split_one(src, hi + (size_t)z * (AM / 4), lo + (size_t)z * (AM / 4), i);
}

__global__ void split_w4(const float4* __restrict__ w0, const float4* __restrict__ w1,
                         const float4* __restrict__ w2, const float4* __restrict__ w3,
                         uint2* __restrict__ hi, uint2* __restrict__ lo)
{
    int i = blockIdx.x * blockDim.x + threadIdx.x;
    int z = blockIdx.y;
    const float4* src = (z == 0) ? w0 : (z == 1) ? w1 : (z == 2) ? w2 : w3;
    split_one(src, hi + (size_t)z * (WM / 4), lo + (size_t)z * (WM / 4), i);
}

// ===========================================================================
// bf16 hi/lo GEMM v2: C = A @ W^T + bias (3 mma products, fp32 accum)
// 128x128 CTA tile, 8 warps (64x32), K-slab 32 (64B logical rows, SW128 swizzle
// on row-pairs -> conflict-free), 3-stage cp.async, 2 CTAs/SM.
// mode 0: fp32 C row-major [M,N].
// mode 1: bf16 hi/lo out, permuted to [B,H,L,64], scaled by `scale`.
// ===========================================================================
#define STAGE_BYTES 32768           // 4 arrays x 128 rows x 64B
#define NSLAB 32
#define GEMM_SMEM (3 * STAGE_BYTES + 1024)   // 99,328 -> 2 CTAs/SM

__global__ __launch_bounds__(256, 2)
void tc_gemm(const __nv_bfloat16* __restrict__ Ahi, const __nv_bfloat16* __restrict__ Alo,
             const __nv_bfloat16* __restrict__ Whi, const __nv_bfloat16* __restrict__ Wlo,
             const float* __restrict__ bias, float* __restrict__ C,
             __nv_bfloat16* __restrict__ Chi, __nv_bfloat16* __restrict__ Clo,
             float scale, int mode)
{
    extern __shared__ char smem_raw[];
    const uint32_t sb = (smem_u32(smem_raw) + 1023u) & ~1023u;

    const int tid  = threadIdx.x;
    const int wrp  = tid >> 5, lane = tid & 31;
    const int m0   = blockIdx.y * 128;
    const int n0   = blockIdx.x * 128;
    const int wm   = (wrp & 1) * 64;
    const int wn   = (wrp >> 1) * 32;

    auto issue = [&](int t, int s) {
        uint32_t st = sb + s * STAGE_BYTES;
#pragma unroll
        for (int sub = 0; sub < 8; ++sub) {
            int idx = sub * 256 + tid;          // 0..2047
            int arr = idx >> 9;                 // 0 Ahi 1 Alo 2 Whi 3 Wlo
            int rem = idx & 511;
            int r   = rem >> 2;                 // 0..127
            int c16 = rem & 3;                  // 16B chunk in 64B row
            uint32_t off = SWZ((uint32_t)(r * 64 + c16 * 16));
            size_t g = (size_t)(((arr < 2) ? m0 : n0) + r) * DMODEL + t * 32 + c16 * 8;
            const __nv_bfloat16* base =
                (arr == 0) ? Ahi : (arr == 1) ? Alo : (arr == 2) ? Whi : Wlo;
            cp16(st + arr * 8192 + off, base + g);
        }
        CP_COMMIT();
    };

    float acc[4][4][4];
#pragma unroll
    for (int a = 0; a < 4; ++a)
#pragma unroll
        for (int b = 0; b < 4; ++b)
#pragma unroll
            for (int c = 0; c < 4; ++c) acc[a][b][c] = 0.f;

    issue(0, 0);
    issue(1, 1);

    const int lr   = lane & 15;
    const int lc   = lane >> 4;
    const int brow = (lane & 7) + ((lane >> 4) & 1) * 8;
    const int bch  = (lane >> 3) & 1;

    for (int t = 0; t < NSLAB; ++t) {
        if (t < NSLAB - 1) CP_WAIT1();
        else               CP_WAIT0();
        __syncthreads();

        uint32_t st  = sb + (t % 3) * STAGE_BYTES;
        uint32_t aHi = st, aLo = st + 8192, wHi = st + 16384, wLo = st + 24576;

#pragma unroll
        for (int kq = 0; kq < 2; ++kq) {
            uint32_t afr[4][4], bh[8], bl[8];
#pragma unroll
            for (int mt = 0; mt < 4; ++mt)
                ldm_x4(afr[mt], aHi + SWZ((wm + mt * 16 + lr) * 64 + kq * 32 + lc * 16));
#pragma unroll
            for (int g = 0; g < 2; ++g) {
                uint32_t o = SWZ((wn + g * 16 + brow) * 64 + kq * 32 + bch * 16);
                ldm_x4(&bh[g * 4], wHi + o);
                ldm_x4(&bl[g * 4], wLo + o);
            }
#pragma unroll
            for (int mt = 0; mt < 4; ++mt)
#pragma unroll
                for (int nt = 0; nt < 4; ++nt) {
                    mma_bf16(acc[mt][nt], afr[mt], &bh[nt * 2]);
                    mma_bf16(acc[mt][nt], afr[mt], &bl[nt * 2]);
                }
#pragma unroll
            for (int mt = 0; mt < 4; ++mt)
                ldm_x4(afr[mt], aLo + SWZ((wm + mt * 16 + lr) * 64 + kq * 32 + lc * 16));
#pragma unroll
            for (int mt = 0; mt < 4; ++mt)
#pragma unroll
                for (int nt = 0; nt < 4; ++nt)
                    mma_bf16(acc[mt][nt], afr[mt], &bh[nt * 2]);
        }

        if (t + 2 < NSLAB) issue(t + 2, (t + 2) % 3);
    }

    const int er = lane >> 2, ec = (lane & 3) * 2;
#pragma unroll
    for (int mt = 0; mt < 4; ++mt) {
#pragma unroll
        for (int nt = 0; nt < 4; ++nt) {
            int gj = n0 + wn + nt * 8 + ec;
            float bb0 = __ldg(bias + gj), bb1 = __ldg(bias + gj + 1);
#pragma unroll
            for (int h2 = 0; h2 < 2; ++h2) {
                int gi = m0 + wm + mt * 16 + er + h2 * 8;
                float v0 = acc[mt][nt][h2 * 2 + 0] + bb0;
                float v1 = acc[mt][nt][h2 * 2 + 1] + bb1;
                if (mode == 0) {
                    *(float2*)(C + (size_t)gi * DMODEL + gj) = make_float2(v0, v1);
                } else {
                    v0 *= scale; v1 *= scale;
                    int bi = gi >> 11, l = gi & 2047;
                    int hh = gj >> 6,  d = gj & 63;
                    size_t idx = ((size_t)((bi * NHEADS + hh) * L_SEQ + l)) * HD + d;
                    *(uint32_t*)(Chi + idx) = pack_hi(v0, v1);
                    *(uint32_t*)(Clo + idx) = pack_lo(v0, v1);
                }
            }
        }
    }
}

// ===========================================================================
// Flash attention — R12-proven (persistent Q frags, __expf, lb(256,1),
// bf16 hi/lo output). UNCHANGED.
// ===========================================================================
#define FL_QHI   8192
#define FL_QLO   24576
#define FL_BUF   40960
#define FL_BUFSZ 32768
#define FLASH_SMEM (1024 + FL_BUF + 2 * FL_BUFSZ)

#define NEG_INF __int_as_float(0xff800000)

__global__ __launch_bounds__(256, 1)
void flash_mma(const __nv_bfloat16* __restrict__ Qhi, const __nv_bfloat16* __restrict__ Qlo,
               const __nv_bfloat16* __restrict__ Khi, const __nv_bfloat16* __restrict__ Klo,
               const __nv_bfloat16* __restrict__ Vhi, const __nv_bfloat16* __restrict__ Vlo,
               const float* __restrict__ rel,
               __nv_bfloat16* __restrict__ Ohi, __nv_bfloat16* __restrict__ Olo)
{
    extern __shared__ char fsm[];
    const uint32_t sb = (smem_u32(fsm) + 1023u) & ~1023u;
    float* LUT = (float*)(fsm + (sb - smem_u32(fsm)));

    const int tid  = threadIdx.x;
    const int wrp  = tid >> 5, lane = tid & 31;
    const int qi   = (int)gridDim.x - 1 - (int)blockIdx.x;   // heavy first
    const int bh   = blockIdx.y;
    const int h    = bh & (NHEADS - 1);
    const int b    = bh >> 4;
    const int q0   = qi * 128;
    const int wq   = wrp * 16;
    const int nk   = 2 * qi + 2;

    // bias LUT over n = q-k in [0,2047]
    for (int n = tid; n < 2048; n += 256) {
        int bucket;
        if (n < 16) bucket = n;
        else {
            bucket = 16 + (int)(log((double)n * (1.0 / 16.0)) * (16.0 / log(8.0)));
            if (bucket > 31) bucket = 31;
        }
        LUT[n] = rel[bucket * NHEADS + h];
    }

    // async-load Q tile (hi+lo)
    {
#pragma unroll
        for (int i = 0; i < 8; ++i) {
            int idx = tid + i * 256;
            int arr = idx >> 10;
            int rem = idx & 1023;
            int r = rem >> 3, c16 = rem & 7;
            const __nv_bfloat16* src = (arr ? Qlo : Qhi)
                + ((size_t)(bh * L_SEQ + q0 + r)) * HD + c16 * 8;
            cp16(sb + (arr ? FL_QLO : FL_QHI) + SWZ(r * 128 + c16 * 16), src);
        }
        CP_COMMIT();
    }

    auto issueKV = [&](int kt) {
        uint32_t buf = sb + FL_BUF + (kt & 1) * FL_BUFSZ;
        int k0 = kt * 64;
#pragma unroll
        for (int i = 0; i < 8; ++i) {
            int idx = tid + i * 256;
            int arr = idx >> 9;               // 0 Khi 1 Klo 2 Vhi 3 Vlo
            int rem = idx & 511;
            int r = rem >> 3, c16 = rem & 7;
            const __nv_bfloat16* base =
                (arr == 0) ? Khi : (arr == 1) ? Klo : (arr == 2) ? Vhi : Vlo;
            const __nv_bfloat16* src = base
                + ((size_t)(bh * L_SEQ + k0 + r)) * HD + c16 * 8;
            cp16(buf + arr * 8192 + SWZ(r * 128 + c16 * 16), src);
        }
        CP_COMMIT();
    };

    issueKV(0);
    CP_WAIT0();
    __syncthreads();

    // Q fragments (persist in registers)
    uint32_t qh[4][4], ql[4][4];
    {
        const int lr = lane & 15, lc = lane >> 4;
#pragma unroll
        for (int kc = 0; kc < 4; ++kc) {
            uint32_t o = SWZ((wq + lr) * 128 + kc * 32 + lc * 16);
            ldm_x4(qh[kc], sb + FL_QHI + o);
            ldm_x4(ql[kc], sb + FL_QLO + o);
        }
    }

    float O[8][4];
#pragma unroll
    for (int i = 0; i < 8; ++i)
#pragma unroll
        for (int j = 0; j < 4; ++j) O[i][j] = 0.f;
    float m0r = NEG_INF, m1r = NEG_INF, l0r = 0.f, l1r = 0.f;

    const int brow = (lane & 7) + ((lane >> 4) & 1) * 8;
    const int bch  = (lane >> 3) & 1;
    const int vrow = (lane & 7) + ((lane >> 3) & 1) * 8;
    const int vch  = lane >> 4;
    const int er   = lane >> 2, ec = (lane & 3) * 2;
    const int qr0  = q0 + wq + er;

    for (int kt = 0; kt < nk; ++kt) {
        if (kt + 1 < nk) issueKV(kt + 1);
        const uint32_t kb = sb + FL_BUF + (kt & 1) * FL_BUFSZ;
        const int k0 = kt * 64;

        // ---- S = (Q/8) K^T -------------------------------------------------
        float S[8][4];
#pragma unroll
        for (int i = 0; i < 8; ++i)
#pragma unroll
            for (int j = 0; j < 4; ++j) S[i][j] = 0.f;

#pragma unroll
        for (int kc = 0; kc < 4; ++kc) {
            uint32_t kh[16], kl[16];
#pragma unroll
            for (int kg = 0; kg < 4; ++kg) {
                uint32_t o = SWZ((kg * 16 + brow) * 128 + kc * 32 + bch * 16);
                ldm_x4(&kh[kg * 4], kb + o);
                ldm_x4(&kl[kg * 4], kb + 8192 + o);
            }
#pragma unroll
            for (int nt = 0; nt < 8; ++nt) {
                mma_bf16(S[nt], qh[kc], &kh[nt * 2]);
                mma_bf16(S[nt], qh[kc], &kl[nt * 2]);
                mma_bf16(S[nt], ql[kc], &kh[nt * 2]);
            }
        }

        // ---- bias + mask + online softmax ---------------------------------
        const bool msk = (kt >= 2 * qi);
        float tm0 = NEG_INF, tm1 = NEG_INF;
#pragma unroll
        for (int nt = 0; nt < 8; ++nt) {
            int kk = k0 + nt * 8 + ec;
            if (msk) {
#pragma unroll
                for (int j = 0; j < 2; ++j) {
                    int k = kk + j;
                    S[nt][j]     = (k <= qr0)     ? S[nt][j]     + LUT[qr0 - k]     : NEG_INF;
                    S[nt][j + 2] = (k <= qr0 + 8) ? S[nt][j + 2] + LUT[qr0 + 8 - k] : NEG_INF;
                }
            } else {
#pragma unroll
                for (int j = 0; j < 2; ++j) {
                    S[nt][j]     += LUT[qr0 - kk - j];
                    S[nt][j + 2] += LUT[qr0 + 8 - kk - j];
                }
            }
            tm0 = fmaxf(tm0, fmaxf(S[nt][0], S[nt][1]));
            tm1 = fmaxf(tm1, fmaxf(S[nt][2], S[nt][3]));
        }
#pragma unroll
        for (int d = 1; d < 4; d <<= 1) {
            tm0 = fmaxf(tm0, __shfl_xor_sync(0xffffffffu, tm0, d));
            tm1 = fmaxf(tm1, __shfl_xor_sync(0xffffffffu, tm1, d));
        }
        float mn0 = fmaxf(m0r, tm0), mn1 = fmaxf(m1r, tm1);
        float a0 = __expf(m0r - mn0), a1 = __expf(m1r - mn1);
        m0r = mn0; m1r = mn1;
        float ls0 = 0.f, ls1 = 0.f;
#pragma unroll
        for (int nt = 0; nt < 8; ++nt) {
            S[nt][0] = __expf(S[nt][0] - mn0); ls0 += S[nt][0];
            S[nt][1] = __expf(S[nt][1] - mn0); ls0 += S[nt][1];
            S[nt][2] = __expf(S[nt][2] - mn1); ls1 += S[nt][2];
            S[nt][3] = __expf(S[nt][3] - mn1); ls1 += S[nt][3];
        }
#pragma unroll
        for (int d = 1; d < 4; d <<= 1) {
            ls0 += __shfl_xor_sync(0xffffffffu, ls0, d);
            ls1 += __shfl_xor_sync(0xffffffffu, ls1, d);
        }
        l0r = l0r * a0 + ls0;
        l1r = l1r * a1 + ls1;
#pragma unroll
        for (int nt = 0; nt < 8; ++nt) {
            O[nt][0] *= a0; O[nt][1] *= a0;
            O[nt][2] *= a1; O[nt][3] *= a1;
        }

        // ---- O += P V  (P packed in registers, V via ldmatrix.trans) ------
#pragma unroll
        for (int kc = 0; kc < 4; ++kc) {
            const int t0 = kc * 2, t1 = kc * 2 + 1;
            uint32_t ph[4], pl[4];
            ph[0] = pack_hi(S[t0][0], S[t0][1]);
            ph[1] = pack_hi(S[t0][2], S[t0][3]);
            ph[2] = pack_hi(S[t1][0], S[t1][1]);
            ph[3] = pack_hi(S[t1][2], S[t1][3]);
            pl[0] = pack_lo(S[t0][0], S[t0][1]);
            pl[1] = pack_lo(S[t0][2], S[t0][3]);
            pl[2] = pack_lo(S[t1][0], S[t1][1]);
            pl[3] = pack_lo(S[t1][2], S[t1][3]);
#pragma unroll
            for (int dt = 0; dt < 4; ++dt) {
                uint32_t vh[4], vl[4];
                uint32_t o = SWZ((kc * 16 + vrow) * 128 + dt * 32 + vch * 16);
                ldm_x4_t(vh, kb + 16384 + o);
                ldm_x4_t(vl, kb + 24576 + o);
#pragma unroll
                for (int g = 0; g < 2; ++g) {
                    int nt = dt * 2 + g;
                    mma_bf16(O[nt], ph, &vh[g * 2]);
                    mma_bf16(O[nt], ph, &vl[g * 2]);
                    mma_bf16(O[nt], pl, &vh[g * 2]);
                }
            }
        }

        if (kt + 1 < nk) { CP_WAIT0(); __syncthreads(); }
    }

    // ---- normalize + write bf16 hi/lo in [B, L, H*64] ----------------------
    const float inv0 = 1.0f / l0r, inv1 = 1.0f / l1r;
#pragma unroll
    for (int nt = 0; nt < 8; ++nt) {
        int d = nt * 8 + ec;
        size_t i0 = ((size_t)(b * L_SEQ + qr0)     * NHEADS + h) * HD + d;
        size_t i1 = ((size_t)(b * L_SEQ + qr0 + 8) * NHEADS + h) * HD + d;
        float v00 = O[nt][0] * inv0, v01 = O[nt][1] * inv0;
        float v10 = O[nt][2] * inv1, v11 = O[nt][3] * inv1;
        *(uint32_t*)(Ohi + i0) = pack_hi(v00, v01);
        *(uint32_t*)(Olo + i0) = pack_lo(v00, v01);
        *(uint32_t*)(Ohi + i1) = pack_hi(v10, v11);
        *(uint32_t*)(Olo + i1) = pack_lo(v10, v11);
    }
}

// ===========================================================================
extern "C" void kernel_launch(void* const* d_in, const int* in_sizes, int n_in,
                              void* d_out, int out_size)
{
    const float* query = (const float*)d_in[0];
    const float* key   = (const float*)d_in[1];
    const float* value = (const float*)d_in[2];
    const float* Wq    = (const float*)d_in[5];
    const float* bq    = (const float*)d_in[6];
    const float* Wk    = (const float*)d_in[7];
    const float* bk    = (const float*)d_in[8];
    const float* Wv    = (const float*)d_in[9];
    const float* bv    = (const float*)d_in[10];
    const float* Wo    = (const float*)d_in[11];
    const float* bo    = (const float*)d_in[12];
    const float* rel   = (const float*)d_in[13];

    __nv_bfloat16 *Ih, *Il, *Wh, *Wl;
    __nv_bfloat16 *Qhi, *Qlo, *Khi, *Klo, *Vhi, *Vlo, *Ohi, *Olo;
    cudaGetSymbolAddress((void**)&Ih,  g_Ih);
    cudaGetSymbolAddress((void**)&Il,  g_Il);
    cudaGetSymbolAddress((void**)&Wh,  g_Wh);
    cudaGetSymbolAddress((void**)&Wl,  g_Wl);
    cudaGetSymbolAddress((void**)&Qhi, g_Qhi);
    cudaGetSymbolAddress((void**)&Qlo, g_Qlo);
    cudaGetSymbolAddress((void**)&Khi, g_Khi);
    cudaGetSymbolAddress((void**)&Klo, g_Klo);
    cudaGetSymbolAddress((void**)&Vhi, g_Vhi);
    cudaGetSymbolAddress((void**)&Vlo, g_Vlo);
    cudaGetSymbolAddress((void**)&Ohi, g_Ohi);
    cudaGetSymbolAddress((void**)&Olo, g_Olo);

    cudaFuncSetAttribute(tc_gemm,   cudaFuncAttributeMaxDynamicSharedMemorySize, GEMM_SMEM);
    cudaFuncSetAttribute(flash_mma, cudaFuncAttributeMaxDynamicSharedMemorySize, FLASH_SMEM);

    dim3 gb(DMODEL / 128, MROWS / 128);   // (8, 32)

    // 1) batched splits
    split_in3<<<dim3(AM / 4 / 256, 3), 256>>>((const float4*)query, (const float4*)key,
                                              (const float4*)value, (uint2*)Ih, (uint2*)Il);
    split_w4<<<dim3(WM / 4 / 256, 4), 256>>>((const float4*)Wq, (const float4*)Wk,
                                             (const float4*)Wv, (const float4*)Wo,
                                             (uint2*)Wh, (uint2*)Wl);

    // 2) projections; Q pre-scaled by 0.125
    tc_gemm<<<gb, 256, GEMM_SMEM>>>(Ih,            Il,            Wh,            Wl,
                                    bq, nullptr, Qhi, Qlo, 0.125f, 1);
    tc_gemm<<<gb, 256, GEMM_SMEM>>>(Ih + (size_t)1 * AM, Il + (size_t)1 * AM,
                                    Wh + (size_t)1 * WM, Wl + (size_t)1 * WM,
                                    bk, nullptr, Khi, Klo, 1.0f, 1);
    tc_gemm<<<gb, 256, GEMM_SMEM>>>(Ih + (size_t)2 * AM, Il + (size_t)2 * AM,
                                    Wh + (size_t)2 * WM, Wl + (size_t)2 * WM,
                                    bv, nullptr, Vhi, Vlo, 1.0f, 1);

    // 3) flash attention -> bf16 hi/lo [B,L,D]
    flash_mma<<<dim3(16, 32), 256, FLASH_SMEM>>>(Qhi, Qlo, Khi, Klo, Vhi, Vlo,
                                                 rel, Ohi, Olo);

    // 4) output projection
    tc_gemm<<<gb, 256, GEMM_SMEM>>>(Ohi, Olo,
                                    Wh + (size_t)3 * WM, Wl + (size_t)3 * WM,
                                    bo, (float*)d_out, nullptr, nullptr, 1.0f, 0);
}

// round 15
// speedup vs baseline: 1.0054x; 1.0054x over previous
#include <cuda_runtime.h>
#include <cuda_bf16.h>
#include <math.h>
#include <stdint.h>

#define L_SEQ   2048
#define BATCH   2
#define NHEADS  16
#define HD      64
#define DMODEL  1024
#define MROWS   (BATCH * L_SEQ)   // 4096
#define BHL     (BATCH * NHEADS * L_SEQ * HD)
#define AM      (MROWS * DMODEL)
#define WM      (DMODEL * DMODEL)

// Scratch (__device__ globals allowed)
__device__ __nv_bfloat16 g_Ih[3 * AM], g_Il[3 * AM];   // split query/key/value
__device__ __nv_bfloat16 g_Wh[4 * WM], g_Wl[4 * WM];   // split Wq,Wk,Wv,Wo
__device__ __nv_bfloat16 g_Qhi[BHL], g_Qlo[BHL];       // [B,H,L,64], scaled 0.125
__device__ __nv_bfloat16 g_Khi[BHL], g_Klo[BHL];
__device__ __nv_bfloat16 g_Vhi[BHL], g_Vlo[BHL];
__device__ __nv_bfloat16 g_Ohi[AM], g_Olo[AM];         // attn out, [B,L,D] hi/lo

// ===========================================================================
// helpers (baseline PTX: ldmatrix sm_75+, mma.bf16 sm_80+, cp.async sm_80+)
// ===========================================================================
__device__ __forceinline__ uint32_t smem_u32(const void* p) {
    return (uint32_t)__cvta_generic_to_shared(p);
}
#define SWZ(off) (((uint32_t)(off)) ^ ((((uint32_t)(off)) >> 3) & 0x70))

__device__ __forceinline__ void cp16(uint32_t dst, const void* src) {
    asm volatile("cp.async.ca.shared.global [%0], [%1], 16;"
                 :: "r"(dst), "l"(src) : "memory");
}
#define CP_COMMIT() asm volatile("cp.async.commit_group;" ::: "memory")
#define CP_WAIT0()  asm volatile("cp.async.wait_group 0;" ::: "memory")
#define CP_WAIT1()  asm volatile("cp.async.wait_group 1;" ::: "memory")

__device__ __forceinline__ void ldm_x4(uint32_t* r, uint32_t addr) {
    asm volatile("ldmatrix.sync.aligned.m8n8.x4.shared.b16 {%0,%1,%2,%3}, [%4];"
                 : "=r"(r[0]), "=r"(r[1]), "=r"(r[2]), "=r"(r[3]) : "r"(addr));
}
__device__ __forceinline__ void ldm_x4_t(uint32_t* r, uint32_t addr) {
    asm volatile("ldmatrix.sync.aligned.m8n8.x4.trans.shared.b16 {%0,%1,%2,%3}, [%4];"
                 : "=r"(r[0]), "=r"(r[1]), "=r"(r[2]), "=r"(r[3]) : "r"(addr));
}
__device__ __forceinline__ void mma_bf16(float* d, const uint32_t* a, const uint32_t* b) {
    asm volatile("mma.sync.aligned.m16n8k16.row.col.f32.bf16.bf16.f32 "
                 "{%0,%1,%2,%3}, {%4,%5,%6,%7}, {%8,%9}, {%0,%1,%2,%3};"
                 : "+f"(d[0]), "+f"(d[1]), "+f"(d[2]), "+f"(d[3])
                 : "r"(a[0]), "r"(a[1]), "r"(a[2]), "r"(a[3]),
                   "r"(b[0]), "r"(b[1]));
}
__device__ __forceinline__ uint32_t pack_hi(float a, float b) {
    return __byte_perm(__float_as_uint(a), __float_as_uint(b), 0x7632);
}
__device__ __forceinline__ uint32_t pack_lo(float a, float b) {
    float ra = a - __uint_as_float(__float_as_uint(a) & 0xffff0000u);
    float rb = b - __uint_as_float(__float_as_uint(b) & 0xffff0000u);
    uint32_t r;
    asm("cvt.rn.satfinite.bf16x2.f32 %0, %1, %2;" : "=r"(r) : "f"(rb), "f"(ra));
    return r;
}

// ===========================================================================
// batched fp32 -> bf16 hi/lo split kernels
// ===========================================================================
__device__ __forceinline__ void split_one(const float4* src, uint2* hi, uint2* lo, int i) {
    float4 v = src[i];
    uint2 h, l;
    h.x = pack_hi(v.x, v.y);  h.y = pack_hi(v.z, v.w);
    l.x = pack_lo(v.x, v.y);  l.y = pack_lo(v.z, v.w);
    hi[i] = h;  lo[i] = l;
}

__global__ void split_in3(const float4* __restrict__ q, const float4* __restrict__ k,
                          const float4* __restrict__ v,
                          uint2* __restrict__ hi, uint2* __restrict__ lo)
{
    int i = blockIdx.x * blockDim.x + threadIdx.x;
    int z = blockIdx.y;
    const float4* src = (z == 0) ? q : (z == 1) ? k : v;
    split_one(src, hi + (size_t)z * (AM / 4), lo + (size_t)z * (AM / 4), i);
}

__global__ void split_w4(const float4* __restrict__ w0, const float4* __restrict__ w1,
                         const float4* __restrict__ w2, const float4* __restrict__ w3,
                         uint2* __restrict__ hi, uint2* __restrict__ lo)
{
    int i = blockIdx.x * blockDim.x + threadIdx.x;
    int z = blockIdx.y;
    const float4* src = (z == 0) ? w0 : (z == 1) ? w1 : (z == 2) ? w2 : w3;
    split_one(src, hi + (size_t)z * (WM / 4), lo + (size_t)z * (WM / 4), i);
}

// ===========================================================================
// bf16 hi/lo GEMM v3: C = A @ W^T + bias (3 mma products, fp32 accum)
// 128x256 CTA tile (grid 4x32 = 128 CTAs = one full wave), 8 warps (64x64),
// K-slab 64, 2-stage cp.async, 1 CTA/SM.
// mode 0: fp32 C row-major [M,N].
// mode 1: bf16 hi/lo out, permuted to [B,H,L,64], scaled by `scale`.
// ===========================================================================
#define STAGE_BYTES 98304            // Ahi,Alo 16KB ea + Whi,Wlo 32KB ea
#define GEMM_SMEM (2 * STAGE_BYTES + 1024)   // 197,632 -> 1 CTA/SM

__global__ __launch_bounds__(256, 1)
void tc_gemm(const __nv_bfloat16* __restrict__ Ahi, const __nv_bfloat16* __restrict__ Alo,
             const __nv_bfloat16* __restrict__ Whi, const __nv_bfloat16* __restrict__ Wlo,
             const float* __restrict__ bias, float* __restrict__ C,
             __nv_bfloat16* __restrict__ Chi, __nv_bfloat16* __restrict__ Clo,
             float scale, int mode)
{
    extern __shared__ char smem_raw[];
    const uint32_t sb = (smem_u32(smem_raw) + 1023u) & ~1023u;

    const int tid  = threadIdx.x;
    const int wrp  = tid >> 5, lane = tid & 31;
    const int m0   = blockIdx.y * 128;
    const int n0   = blockIdx.x * 256;
    const int wm   = (wrp & 1) * 64;
    const int wn   = (wrp >> 1) * 64;

    // async copy of slab t (64 K-cols) into stage s: A 128 rows, W 256 rows
    auto issue = [&](int t, int s) {
        uint32_t st = sb + s * STAGE_BYTES;
#pragma unroll
        for (int sub = 0; sub < 24; ++sub) {
            int idx = sub * 256 + tid;          // 0..6143 (region uniform per sub)
            if (idx < 2048) {                   // A: hi 0..1023, lo 1024..2047
                int arr = idx >> 10;
                int rem = idx & 1023;
                int r = rem >> 3, c16 = rem & 7;
                const __nv_bfloat16* base = arr ? Alo : Ahi;
                cp16(st + arr * 16384 + SWZ(r * 128 + c16 * 16),
                     base + (size_t)(m0 + r) * DMODEL + t * 64 + c16 * 8);
            } else {                            // W: hi 0..2047, lo 2048..4095
                int idx2 = idx - 2048;
                int arr = idx2 >> 11;
                int rem = idx2 & 2047;
                int r = rem >> 3, c16 = rem & 7;
                const __nv_bfloat16* base = arr ? Wlo : Whi;
                cp16(st + 32768 + arr * 32768 + SWZ(r * 128 + c16 * 16),
                     base + (size_t)(n0 + r) * DMODEL + t * 64 + c16 * 8);
            }
        }
        CP_COMMIT();
    };

    float acc[4][8][4];
#pragma unroll
    for (int a = 0; a < 4; ++a)
#pragma unroll
        for (int b = 0; b < 8; ++b)
#pragma unroll
            for (int c = 0; c < 4; ++c) acc[a][b][c] = 0.f;

    issue(0, 0);
    issue(1, 1);

    const int lr   = lane & 15;
    const int lc   = lane >> 4;
    const int brow = (lane & 7) + ((lane >> 4) & 1) * 8;
    const int bch  = (lane >> 3) & 1;

    for (int t = 0; t < 16; ++t) {
        if (t < 15) CP_WAIT1();
        else        CP_WAIT0();
        __syncthreads();

        uint32_t st  = sb + (t & 1) * STAGE_BYTES;
        uint32_t aHi = st, aLo = st + 16384, wHi = st + 32768, wLo = st + 65536;

#pragma unroll
        for (int kq = 0; kq < 4; ++kq) {
            uint32_t afr[4][4], bh[16], bl[16];
#pragma unroll
            for (int mt = 0; mt < 4; ++mt)
                ldm_x4(afr[mt], aHi + SWZ((wm + mt * 16 + lr) * 128 + kq * 32 + lc * 16));
#pragma unroll
            for (int g = 0; g < 4; ++g) {
                uint32_t o = SWZ((wn + g * 16 + brow) * 128 + kq * 32 + bch * 16);
                ldm_x4(&bh[g * 4], wHi + o);
                ldm_x4(&bl[g * 4], wLo + o);
            }
#pragma unroll
            for (int mt = 0; mt < 4; ++mt)
#pragma unroll
                for (int nt = 0; nt < 8; ++nt) {
                    mma_bf16(acc[mt][nt], afr[mt], &bh[nt * 2]);
                    mma_bf16(acc[mt][nt], afr[mt], &bl[nt * 2]);
                }
#pragma unroll
            for (int mt = 0; mt < 4; ++mt)
                ldm_x4(afr[mt], aLo + SWZ((wm + mt * 16 + lr) * 128 + kq * 32 + lc * 16));
#pragma unroll
            for (int mt = 0; mt < 4; ++mt)
#pragma unroll
                for (int nt = 0; nt < 8; ++nt)
                    mma_bf16(acc[mt][nt], afr[mt], &bh[nt * 2]);
        }

        // all warps done reading this stage before it is refilled
        __syncthreads();
        if (t + 2 < 16) issue(t + 2, t & 1);
    }

    const int er = lane >> 2, ec = (lane & 3) * 2;
#pragma unroll
    for (int mt = 0; mt < 4; ++mt) {
#pragma unroll
        for (int nt = 0; nt < 8; ++nt) {
            int gj = n0 + wn + nt * 8 + ec;
            float bb0 = __ldg(bias + gj), bb1 = __ldg(bias + gj + 1);
#pragma unroll
            for (int h2 = 0; h2 < 2; ++h2) {
                int gi = m0 + wm + mt * 16 + er + h2 * 8;
                float v0 = acc[mt][nt][h2 * 2 + 0] + bb0;
                float v1 = acc[mt][nt][h2 * 2 + 1] + bb1;
                if (mode == 0) {
                    *(float2*)(C + (size_t)gi * DMODEL + gj) = make_float2(v0, v1);
                } else {
                    v0 *= scale; v1 *= scale;
                    int bi = gi >> 11, l = gi & 2047;
                    int hh = gj >> 6,  d = gj & 63;
                    size_t idx = ((size_t)((bi * NHEADS + hh) * L_SEQ + l)) * HD + d;
                    *(uint32_t*)(Chi + idx) = pack_hi(v0, v1);
                    *(uint32_t*)(Clo + idx) = pack_lo(v0, v1);
                }
            }
        }
    }
}

// ===========================================================================
// Flash attention — R12-proven (persistent Q frags, __expf, lb(256,1),
// bf16 hi/lo output). UNCHANGED.
// ===========================================================================
#define FL_QHI   8192
#define FL_QLO   24576
#define FL_BUF   40960
#define FL_BUFSZ 32768
#define FLASH_SMEM (1024 + FL_BUF + 2 * FL_BUFSZ)

#define NEG_INF __int_as_float(0xff800000)

__global__ __launch_bounds__(256, 1)
void flash_mma(const __nv_bfloat16* __restrict__ Qhi, const __nv_bfloat16* __restrict__ Qlo,
               const __nv_bfloat16* __restrict__ Khi, const __nv_bfloat16* __restrict__ Klo,
               const __nv_bfloat16* __restrict__ Vhi, const __nv_bfloat16* __restrict__ Vlo,
               const float* __restrict__ rel,
               __nv_bfloat16* __restrict__ Ohi, __nv_bfloat16* __restrict__ Olo)
{
    extern __shared__ char fsm[];
    const uint32_t sb = (smem_u32(fsm) + 1023u) & ~1023u;
    float* LUT = (float*)(fsm + (sb - smem_u32(fsm)));

    const int tid  = threadIdx.x;
    const int wrp  = tid >> 5, lane = tid & 31;
    const int qi   = (int)gridDim.x - 1 - (int)blockIdx.x;   // heavy first
    const int bh   = blockIdx.y;
    const int h    = bh & (NHEADS - 1);
    const int b    = bh >> 4;
    const int q0   = qi * 128;
    const int wq   = wrp * 16;
    const int nk   = 2 * qi + 2;

    // bias LUT over n = q-k in [0,2047]
    for (int n = tid; n < 2048; n += 256) {
        int bucket;
        if (n < 16) bucket = n;
        else {
            bucket = 16 + (int)(log((double)n * (1.0 / 16.0)) * (16.0 / log(8.0)));
            if (bucket > 31) bucket = 31;
        }
        LUT[n] = rel[bucket * NHEADS + h];
    }

    // async-load Q tile (hi+lo)
    {
#pragma unroll
        for (int i = 0; i < 8; ++i) {
            int idx = tid + i * 256;
            int arr = idx >> 10;
            int rem = idx & 1023;
            int r = rem >> 3, c16 = rem & 7;
            const __nv_bfloat16* src = (arr ? Qlo : Qhi)
                + ((size_t)(bh * L_SEQ + q0 + r)) * HD + c16 * 8;
            cp16(sb + (arr ? FL_QLO : FL_QHI) + SWZ(r * 128 + c16 * 16), src);
        }
        CP_COMMIT();
    }

    auto issueKV = [&](int kt) {
        uint32_t buf = sb + FL_BUF + (kt & 1) * FL_BUFSZ;
        int k0 = kt * 64;
#pragma unroll
        for (int i = 0; i < 8; ++i) {
            int idx = tid + i * 256;
            int arr = idx >> 9;               // 0 Khi 1 Klo 2 Vhi 3 Vlo
            int rem = idx & 511;
            int r = rem >> 3, c16 = rem & 7;
            const __nv_bfloat16* base =
                (arr == 0) ? Khi : (arr == 1) ? Klo : (arr == 2) ? Vhi : Vlo;
            const __nv_bfloat16* src = base
                + ((size_t)(bh * L_SEQ + k0 + r)) * HD + c16 * 8;
            cp16(buf + arr * 8192 + SWZ(r * 128 + c16 * 16), src);
        }
        CP_COMMIT();
    };

    issueKV(0);
    CP_WAIT0();
    __syncthreads();

    // Q fragments (persist in registers)
    uint32_t qh[4][4], ql[4][4];
    {
        const int lr = lane & 15, lc = lane >> 4;
#pragma unroll
        for (int kc = 0; kc < 4; ++kc) {
            uint32_t o = SWZ((wq + lr) * 128 + kc * 32 + lc * 16);
            ldm_x4(qh[kc], sb + FL_QHI + o);
            ldm_x4(ql[kc], sb + FL_QLO + o);
        }
    }

    float O[8][4];
#pragma unroll
    for (int i = 0; i < 8; ++i)
#pragma unroll
        for (int j = 0; j < 4; ++j) O[i][j] = 0.f;
    float m0r = NEG_INF, m1r = NEG_INF, l0r = 0.f, l1r = 0.f;

    const int brow = (lane & 7) + ((lane >> 4) & 1) * 8;
    const int bch  = (lane >> 3) & 1;
    const int vrow = (lane & 7) + ((lane >> 3) & 1) * 8;
    const int vch  = lane >> 4;
    const int er   = lane >> 2, ec = (lane & 3) * 2;
    const int qr0  = q0 + wq + er;

    for (int kt = 0; kt < nk; ++kt) {
        if (kt + 1 < nk) issueKV(kt + 1);
        const uint32_t kb = sb + FL_BUF + (kt & 1) * FL_BUFSZ;
        const int k0 = kt * 64;

        // ---- S = (Q/8) K^T -------------------------------------------------
        float S[8][4];
#pragma unroll
        for (int i = 0; i < 8; ++i)
#pragma unroll
            for (int j = 0; j < 4; ++j) S[i][j] = 0.f;

#pragma unroll
        for (int kc = 0; kc < 4; ++kc) {
            uint32_t kh[16], kl[16];
#pragma unroll
            for (int kg = 0; kg < 4; ++kg) {
                uint32_t o = SWZ((kg * 16 + brow) * 128 + kc * 32 + bch * 16);
                ldm_x4(&kh[kg * 4], kb + o);
                ldm_x4(&kl[kg * 4], kb + 8192 + o);
            }
#pragma unroll
            for (int nt = 0; nt < 8; ++nt) {
                mma_bf16(S[nt], qh[kc], &kh[nt * 2]);
                mma_bf16(S[nt], qh[kc], &kl[nt * 2]);
                mma_bf16(S[nt], ql[kc], &kh[nt * 2]);
            }
        }

        // ---- bias + mask + online softmax ---------------------------------
        const bool msk = (kt >= 2 * qi);
        float tm0 = NEG_INF, tm1 = NEG_INF;
#pragma unroll
        for (int nt = 0; nt < 8; ++nt) {
            int kk = k0 + nt * 8 + ec;
            if (msk) {
#pragma unroll
                for (int j = 0; j < 2; ++j) {
                    int k = kk + j;
                    S[nt][j]     = (k <= qr0)     ? S[nt][j]     + LUT[qr0 - k]     : NEG_INF;
                    S[nt][j + 2] = (k <= qr0 + 8) ? S[nt][j + 2] + LUT[qr0 + 8 - k] : NEG_INF;
                }
            } else {
#pragma unroll
                for (int j = 0; j < 2; ++j) {
                    S[nt][j]     += LUT[qr0 - kk - j];
                    S[nt][j + 2] += LUT[qr0 + 8 - kk - j];
                }
            }
            tm0 = fmaxf(tm0, fmaxf(S[nt][0], S[nt][1]));
            tm1 = fmaxf(tm1, fmaxf(S[nt][2], S[nt][3]));
        }
#pragma unroll
        for (int d = 1; d < 4; d <<= 1) {
            tm0 = fmaxf(tm0, __shfl_xor_sync(0xffffffffu, tm0, d));
            tm1 = fmaxf(tm1, __shfl_xor_sync(0xffffffffu, tm1, d));
        }
        float mn0 = fmaxf(m0r, tm0), mn1 = fmaxf(m1r, tm1);
        float a0 = __expf(m0r - mn0), a1 = __expf(m1r - mn1);
        m0r = mn0; m1r = mn1;
        float ls0 = 0.f, ls1 = 0.f;
#pragma unroll
        for (int nt = 0; nt < 8; ++nt) {
            S[nt][0] = __expf(S[nt][0] - mn0); ls0 += S[nt][0];
            S[nt][1] = __expf(S[nt][1] - mn0); ls0 += S[nt][1];
            S[nt][2] = __expf(S[nt][2] - mn1); ls1 += S[nt][2];
            S[nt][3] = __expf(S[nt][3] - mn1); ls1 += S[nt][3];
        }
#pragma unroll
        for (int d = 1; d < 4; d <<= 1) {
            ls0 += __shfl_xor_sync(0xffffffffu, ls0, d);
            ls1 += __shfl_xor_sync(0xffffffffu, ls1, d);
        }
        l0r = l0r * a0 + ls0;
        l1r = l1r * a1 + ls1;
#pragma unroll
        for (int nt = 0; nt < 8; ++nt) {
            O[nt][0] *= a0; O[nt][1] *= a0;
            O[nt][2] *= a1; O[nt][3] *= a1;
        }

        // ---- O += P V  (P packed in registers, V via ldmatrix.trans) ------
#pragma unroll
        for (int kc = 0; kc < 4; ++kc) {
            const int t0 = kc * 2, t1 = kc * 2 + 1;
            uint32_t ph[4], pl[4];
            ph[0] = pack_hi(S[t0][0], S[t0][1]);
            ph[1] = pack_hi(S[t0][2], S[t0][3]);
            ph[2] = pack_hi(S[t1][0], S[t1][1]);
            ph[3] = pack_hi(S[t1][2], S[t1][3]);
            pl[0] = pack_lo(S[t0][0], S[t0][1]);
            pl[1] = pack_lo(S[t0][2], S[t0][3]);
            pl[2] = pack_lo(S[t1][0], S[t1][1]);
            pl[3] = pack_lo(S[t1][2], S[t1][3]);
#pragma unroll
            for (int dt = 0; dt < 4; ++dt) {
                uint32_t vh[4], vl[4];
                uint32_t o = SWZ((kc * 16 + vrow) * 128 + dt * 32 + vch * 16);
                ldm_x4_t(vh, kb + 16384 + o);
                ldm_x4_t(vl, kb + 24576 + o);
#pragma unroll
                for (int g = 0; g < 2; ++g) {
                    int nt = dt * 2 + g;
                    mma_bf16(O[nt], ph, &vh[g * 2]);
                    mma_bf16(O[nt], ph, &vl[g * 2]);
                    mma_bf16(O[nt], pl, &vh[g * 2]);
                }
            }
        }

        if (kt + 1 < nk) { CP_WAIT0(); __syncthreads(); }
    }

    // ---- normalize + write bf16 hi/lo in [B, L, H*64] ----------------------
    const float inv0 = 1.0f / l0r, inv1 = 1.0f / l1r;
#pragma unroll
    for (int nt = 0; nt < 8; ++nt) {
        int d = nt * 8 + ec;
        size_t i0 = ((size_t)(b * L_SEQ + qr0)     * NHEADS + h) * HD + d;
        size_t i1 = ((size_t)(b * L_SEQ + qr0 + 8) * NHEADS + h) * HD + d;
        float v00 = O[nt][0] * inv0, v01 = O[nt][1] * inv0;
        float v10 = O[nt][2] * inv1, v11 = O[nt][3] * inv1;
        *(uint32_t*)(Ohi + i0) = pack_hi(v00, v01);
        *(uint32_t*)(Olo + i0) = pack_lo(v00, v01);
        *(uint32_t*)(Ohi + i1) = pack_hi(v10, v11);
        *(uint32_t*)(Olo + i1) = pack_lo(v10, v11);
    }
}

// ===========================================================================
extern "C" void kernel_launch(void* const* d_in, const int* in_sizes, int n_in,
                              void* d_out, int out_size)
{
    const float* query = (const float*)d_in[0];
    const float* key   = (const float*)d_in[1];
    const float* value = (const float*)d_in[2];
    const float* Wq    = (const float*)d_in[5];
    const float* bq    = (const float*)d_in[6];
    const float* Wk    = (const float*)d_in[7];
    const float* bk    = (const float*)d_in[8];
    const float* Wv    = (const float*)d_in[9];
    const float* bv    = (const float*)d_in[10];
    const float* Wo    = (const float*)d_in[11];
    const float* bo    = (const float*)d_in[12];
    const float* rel   = (const float*)d_in[13];

    __nv_bfloat16 *Ih, *Il, *Wh, *Wl;
    __nv_bfloat16 *Qhi, *Qlo, *Khi, *Klo, *Vhi, *Vlo, *Ohi, *Olo;
    cudaGetSymbolAddress((void**)&Ih,  g_Ih);
    cudaGetSymbolAddress((void**)&Il,  g_Il);
    cudaGetSymbolAddress((void**)&Wh,  g_Wh);
    cudaGetSymbolAddress((void**)&Wl,  g_Wl);
    cudaGetSymbolAddress((void**)&Qhi, g_Qhi);
    cudaGetSymbolAddress((void**)&Qlo, g_Qlo);
    cudaGetSymbolAddress((void**)&Khi, g_Khi);
    cudaGetSymbolAddress((void**)&Klo, g_Klo);
    cudaGetSymbolAddress((void**)&Vhi, g_Vhi);
    cudaGetSymbolAddress((void**)&Vlo, g_Vlo);
    cudaGetSymbolAddress((void**)&Ohi, g_Ohi);
    cudaGetSymbolAddress((void**)&Olo, g_Olo);

    cudaFuncSetAttribute(tc_gemm,   cudaFuncAttributeMaxDynamicSharedMemorySize, GEMM_SMEM);
    cudaFuncSetAttribute(flash_mma, cudaFuncAttributeMaxDynamicSharedMemorySize, FLASH_SMEM);

    dim3 gb(DMODEL / 256, MROWS / 128);   // (4, 32) = 128 CTAs

    // 1) batched splits
    split_in3<<<dim3(AM / 4 / 256, 3), 256>>>((const float4*)query, (const float4*)key,
                                              (const float4*)value, (uint2*)Ih, (uint2*)Il);
    split_w4<<<dim3(WM / 4 / 256, 4), 256>>>((const float4*)Wq, (const float4*)Wk,
                                             (const float4*)Wv, (const float4*)Wo,
                                             (uint2*)Wh, (uint2*)Wl);

    // 2) projections; Q pre-scaled by 0.125
    tc_gemm<<<gb, 256, GEMM_SMEM>>>(Ih,            Il,            Wh,            Wl,
                                    bq, nullptr, Qhi, Qlo, 0.125f, 1);
    tc_gemm<<<gb, 256, GEMM_SMEM>>>(Ih + (size_t)1 * AM, Il + (size_t)1 * AM,
                                    Wh + (size_t)1 * WM, Wl + (size_t)1 * WM,
                                    bk, nullptr, Khi, Klo, 1.0f, 1);
    tc_gemm<<<gb, 256, GEMM_SMEM>>>(Ih + (size_t)2 * AM, Il + (size_t)2 * AM,
                                    Wh + (size_t)2 * WM, Wl + (size_t)2 * WM,
                                    bv, nullptr, Vhi, Vlo, 1.0f, 1);

    // 3) flash attention -> bf16 hi/lo [B,L,D]
    flash_mma<<<dim3(16, 32), 256, FLASH_SMEM>>>(Qhi, Qlo, Khi, Klo, Vhi, Vlo,
                                                 rel, Ohi, Olo);

    // 4) output projection
    tc_gemm<<<gb, 256, GEMM_SMEM>>>(Ohi, Olo,
                                    Wh + (size_t)3 * WM, Wl + (size_t)3 * WM,
                                    bo, (float*)d_out, nullptr, nullptr, 1.0f, 0);
}

// round 16
// speedup vs baseline: 1.0471x; 1.0414x over previous
#include <cuda_runtime.h>
#include <cuda_bf16.h>
#include <math.h>
#include <stdint.h>

#define L_SEQ   2048
#define BATCH   2
#define NHEADS  16
#define HD      64
#define DMODEL  1024
#define MROWS   (BATCH * L_SEQ)   // 4096
#define BHL     (BATCH * NHEADS * L_SEQ * HD)
#define AM      (MROWS * DMODEL)
#define WM      (DMODEL * DMODEL)

// Scratch (__device__ globals allowed)
__device__ __nv_bfloat16 g_Ih[3 * AM], g_Il[3 * AM];   // split query/key/value
__device__ __nv_bfloat16 g_Wh[4 * WM], g_Wl[4 * WM];   // split Wq,Wk,Wv,Wo
__device__ __nv_bfloat16 g_Qhi[BHL], g_Qlo[BHL];       // [B,H,L,64], scaled 0.125
__device__ __nv_bfloat16 g_Khi[BHL], g_Klo[BHL];
__device__ __nv_bfloat16 g_Vhi[BHL], g_Vlo[BHL];
__device__ __nv_bfloat16 g_Ohi[AM], g_Olo[AM];         // attn out, [B,L,D] hi/lo

// ===========================================================================
// helpers (baseline PTX: ldmatrix sm_75+, mma.bf16 sm_80+, cp.async sm_80+)
// ===========================================================================
__device__ __forceinline__ uint32_t smem_u32(const void* p) {
    return (uint32_t)__cvta_generic_to_shared(p);
}
#define SWZ(off) (((uint32_t)(off)) ^ ((((uint32_t)(off)) >> 3) & 0x70))

__device__ __forceinline__ void cp16(uint32_t dst, const void* src) {
    asm volatile("cp.async.ca.shared.global [%0], [%1], 16;"
                 :: "r"(dst), "l"(src) : "memory");
}
#define CP_COMMIT() asm volatile("cp.async.commit_group;" ::: "memory")
#define CP_WAIT0()  asm volatile("cp.async.wait_group 0;" ::: "memory")
#define CP_WAIT1()  asm volatile("cp.async.wait_group 1;" ::: "memory")

__device__ __forceinline__ void ldm_x4(uint32_t* r, uint32_t addr) {
    asm volatile("ldmatrix.sync.aligned.m8n8.x4.shared.b16 {%0,%1,%2,%3}, [%4];"
                 : "=r"(r[0]), "=r"(r[1]), "=r"(r[2]), "=r"(r[3]) : "r"(addr));
}
__device__ __forceinline__ void ldm_x4_t(uint32_t* r, uint32_t addr) {
    asm volatile("ldmatrix.sync.aligned.m8n8.x4.trans.shared.b16 {%0,%1,%2,%3}, [%4];"
                 : "=r"(r[0]), "=r"(r[1]), "=r"(r[2]), "=r"(r[3]) : "r"(addr));
}
__device__ __forceinline__ void mma_bf16(float* d, const uint32_t* a, const uint32_t* b) {
    asm volatile("mma.sync.aligned.m16n8k16.row.col.f32.bf16.bf16.f32 "
                 "{%0,%1,%2,%3}, {%4,%5,%6,%7}, {%8,%9}, {%0,%1,%2,%3};"
                 : "+f"(d[0]), "+f"(d[1]), "+f"(d[2]), "+f"(d[3])
                 : "r"(a[0]), "r"(a[1]), "r"(a[2]), "r"(a[3]),
                   "r"(b[0]), "r"(b[1]));
}
__device__ __forceinline__ uint32_t pack_hi(float a, float b) {
    return __byte_perm(__float_as_uint(a), __float_as_uint(b), 0x7632);
}
__device__ __forceinline__ uint32_t pack_lo(float a, float b) {
    float ra = a - __uint_as_float(__float_as_uint(a) & 0xffff0000u);
    float rb = b - __uint_as_float(__float_as_uint(b) & 0xffff0000u);
    uint32_t r;
    asm("cvt.rn.satfinite.bf16x2.f32 %0, %1, %2;" : "=r"(r) : "f"(rb), "f"(ra));
    return r;
}

// ===========================================================================
// batched fp32 -> bf16 hi/lo split kernels
// ===========================================================================
__device__ __forceinline__ void split_one(const float4* src, uint2* hi, uint2* lo, int i) {
    float4 v = src[i];
    uint2 h, l;
    h.x = pack_hi(v.x, v.y);  h.y = pack_hi(v.z, v.w);
    l.x = pack_lo(v.x, v.y);  l.y = pack_lo(v.z, v.w);
    hi[i] = h;  lo[i] = l;
}

__global__ void split_in3(const float4* __restrict__ q, const float4* __restrict__ k,
                          const float4* __restrict__ v,
                          uint2* __restrict__ hi, uint2* __restrict__ lo)
{
    int i = blockIdx.x * blockDim.x + threadIdx.x;
    int z = blockIdx.y;
    const float4* src = (z == 0) ? q : (z == 1) ? k : v;
    split_one(src, hi + (size_t)z * (AM / 4), lo + (size_t)z * (AM / 4), i);
}

__global__ void split_w4(const float4* __restrict__ w0, const float4* __restrict__ w1,
                         const float4* __restrict__ w2, const float4* __restrict__ w3,
                         uint2* __restrict__ hi, uint2* __restrict__ lo)
{
    int i = blockIdx.x * blockDim.x + threadIdx.x;
    int z = blockIdx.y;
    const float4* src = (z == 0) ? w0 : (z == 1) ? w1 : (z == 2) ? w2 : w3;
    split_one(src, hi + (size_t)z * (WM / 4), lo + (size_t)z * (WM / 4), i);
}

// ===========================================================================
// bf16 hi/lo GEMM: C = A @ W^T + bias (3 mma products, fp32 accum)
// 128x128 CTA tile, 8 warps (64x32), K-slab 64, 3-stage cp.async (R12 shape)
// + explicit kq-level software pipelining of LDSM vs HMMA (double-buffered
//   fragments; kq+1 loads issued before kq's MMA block).
// mode 0: fp32 C row-major [M,N].
// mode 1: bf16 hi/lo out, permuted to [B,H,L,64], scaled by `scale`.
// ===========================================================================
#define STAGE_BYTES 65536
#define GEMM_SMEM (3 * STAGE_BYTES + 1024)

__global__ __launch_bounds__(256, 1)
void tc_gemm(const __nv_bfloat16* __restrict__ Ahi, const __nv_bfloat16* __restrict__ Alo,
             const __nv_bfloat16* __restrict__ Whi, const __nv_bfloat16* __restrict__ Wlo,
             const float* __restrict__ bias, float* __restrict__ C,
             __nv_bfloat16* __restrict__ Chi, __nv_bfloat16* __restrict__ Clo,
             float scale, int mode)
{
    extern __shared__ char smem_raw[];
    const uint32_t sb = (smem_u32(smem_raw) + 1023u) & ~1023u;

    const int tid  = threadIdx.x;
    const int wrp  = tid >> 5, lane = tid & 31;
    const int m0   = blockIdx.y * 128;
    const int n0   = blockIdx.x * 128;
    const int wm   = (wrp & 1) * 64;
    const int wn   = (wrp >> 1) * 32;

    auto issue = [&](int t, int s) {
        uint32_t st = sb + s * STAGE_BYTES;
#pragma unroll
        for (int sub = 0; sub < 4; ++sub) {
            int idx = sub * 256 + tid;
            int r   = idx >> 3;
            int c16 = idx & 7;
            uint32_t off = SWZ(r * 128 + c16 * 16);
            size_t ga = (size_t)(m0 + r) * DMODEL + t * 64 + c16 * 8;
            size_t gw = (size_t)(n0 + r) * DMODEL + t * 64 + c16 * 8;
            cp16(st +     0 + off, Ahi + ga);
            cp16(st + 16384 + off, Alo + ga);
            cp16(st + 32768 + off, Whi + gw);
            cp16(st + 49152 + off, Wlo + gw);
        }
        CP_COMMIT();
    };

    float acc[4][4][4];
#pragma unroll
    for (int a = 0; a < 4; ++a)
#pragma unroll
        for (int b = 0; b < 4; ++b)
#pragma unroll
            for (int c = 0; c < 4; ++c) acc[a][b][c] = 0.f;

    issue(0, 0);
    issue(1, 1);

    const int lr   = lane & 15;
    const int lc   = lane >> 4;
    const int brow = (lane & 7) + ((lane >> 4) & 1) * 8;
    const int bch  = (lane >> 3) & 1;

    for (int t = 0; t < 16; ++t) {
        if (t < 15) CP_WAIT1();
        else        CP_WAIT0();
        __syncthreads();

        uint32_t st  = sb + (t % 3) * STAGE_BYTES;
        uint32_t aHi = st, aLo = st + 16384, wHi = st + 32768, wLo = st + 49152;

        uint32_t afrH[2][4][4], bh[2][8], bl[2][8], afrL[4][4];

        // preload kq = 0 fragments
#pragma unroll
        for (int mt = 0; mt < 4; ++mt)
            ldm_x4(afrH[0][mt], aHi + SWZ((wm + mt * 16 + lr) * 128 + lc * 16));
#pragma unroll
        for (int g = 0; g < 2; ++g) {
            uint32_t o = SWZ((wn + g * 16 + brow) * 128 + bch * 16);
            ldm_x4(&bh[0][g * 4], wHi + o);
            ldm_x4(&bl[0][g * 4], wLo + o);
        }

#pragma unroll
        for (int kq = 0; kq < 4; ++kq) {
            const int cur = kq & 1, nxt = cur ^ 1;

            // issue next kq's LDSM before this kq's MMAs (latency hidden by HMMA)
            if (kq < 3) {
                const int kn = kq + 1;
#pragma unroll
                for (int mt = 0; mt < 4; ++mt)
                    ldm_x4(afrH[nxt][mt],
                           aHi + SWZ((wm + mt * 16 + lr) * 128 + kn * 32 + lc * 16));
#pragma unroll
                for (int g = 0; g < 2; ++g) {
                    uint32_t o = SWZ((wn + g * 16 + brow) * 128 + kn * 32 + bch * 16);
                    ldm_x4(&bh[nxt][g * 4], wHi + o);
                    ldm_x4(&bl[nxt][g * 4], wLo + o);
                }
            }
            // A-lo fragments for this kq (consumed only in the tail block)
#pragma unroll
            for (int mt = 0; mt < 4; ++mt)
                ldm_x4(afrL[mt],
                       aLo + SWZ((wm + mt * 16 + lr) * 128 + kq * 32 + lc * 16));

#pragma unroll
            for (int mt = 0; mt < 4; ++mt)
#pragma unroll
                for (int nt = 0; nt < 4; ++nt) {
                    mma_bf16(acc[mt][nt], afrH[cur][mt], &bh[cur][nt * 2]);
                    mma_bf16(acc[mt][nt], afrH[cur][mt], &bl[cur][nt * 2]);
                }
#pragma unroll
            for (int mt = 0; mt < 4; ++mt)
#pragma unroll
                for (int nt = 0; nt < 4; ++nt)
                    mma_bf16(acc[mt][nt], afrL[mt], &bh[cur][nt * 2]);
        }

        if (t + 2 < 16) issue(t + 2, (t + 2) % 3);
    }

    const int er = lane >> 2, ec = (lane & 3) * 2;
#pragma unroll
    for (int mt = 0; mt < 4; ++mt) {
#pragma unroll
        for (int nt = 0; nt < 4; ++nt) {
            int gj = n0 + wn + nt * 8 + ec;
            float bb0 = __ldg(bias + gj), bb1 = __ldg(bias + gj + 1);
#pragma unroll
            for (int h2 = 0; h2 < 2; ++h2) {
                int gi = m0 + wm + mt * 16 + er + h2 * 8;
                float v0 = acc[mt][nt][h2 * 2 + 0] + bb0;
                float v1 = acc[mt][nt][h2 * 2 + 1] + bb1;
                if (mode == 0) {
                    *(float2*)(C + (size_t)gi * DMODEL + gj) = make_float2(v0, v1);
                } else {
                    v0 *= scale; v1 *= scale;
                    int bi = gi >> 11, l = gi & 2047;
                    int hh = gj >> 6,  d = gj & 63;
                    size_t idx = ((size_t)((bi * NHEADS + hh) * L_SEQ + l)) * HD + d;
                    *(uint32_t*)(Chi + idx) = pack_hi(v0, v1);
                    *(uint32_t*)(Clo + idx) = pack_lo(v0, v1);
                }
            }
        }
    }
}

// ===========================================================================
// Flash attention — R12-proven (persistent Q frags, __expf, lb(256,1),
// bf16 hi/lo output). UNCHANGED.
// ===========================================================================
#define FL_QHI   8192
#define FL_QLO   24576
#define FL_BUF   40960
#define FL_BUFSZ 32768
#define FLASH_SMEM (1024 + FL_BUF + 2 * FL_BUFSZ)

#define NEG_INF __int_as_float(0xff800000)

__global__ __launch_bounds__(256, 1)
void flash_mma(const __nv_bfloat16* __restrict__ Qhi, const __nv_bfloat16* __restrict__ Qlo,
               const __nv_bfloat16* __restrict__ Khi, const __nv_bfloat16* __restrict__ Klo,
               const __nv_bfloat16* __restrict__ Vhi, const __nv_bfloat16* __restrict__ Vlo,
               const float* __restrict__ rel,
               __nv_bfloat16* __restrict__ Ohi, __nv_bfloat16* __restrict__ Olo)
{
    extern __shared__ char fsm[];
    const uint32_t sb = (smem_u32(fsm) + 1023u) & ~1023u;
    float* LUT = (float*)(fsm + (sb - smem_u32(fsm)));

    const int tid  = threadIdx.x;
    const int wrp  = tid >> 5, lane = tid & 31;
    const int qi   = (int)gridDim.x - 1 - (int)blockIdx.x;   // heavy first
    const int bh   = blockIdx.y;
    const int h    = bh & (NHEADS - 1);
    const int b    = bh >> 4;
    const int q0   = qi * 128;
    const int wq   = wrp * 16;
    const int nk   = 2 * qi + 2;

    // bias LUT over n = q-k in [0,2047]
    for (int n = tid; n < 2048; n += 256) {
        int bucket;
        if (n < 16) bucket = n;
        else {
            bucket = 16 + (int)(log((double)n * (1.0 / 16.0)) * (16.0 / log(8.0)));
            if (bucket > 31) bucket = 31;
        }
        LUT[n] = rel[bucket * NHEADS + h];
    }

    // async-load Q tile (hi+lo)
    {
#pragma unroll
        for (int i = 0; i < 8; ++i) {
            int idx = tid + i * 256;
            int arr = idx >> 10;
            int rem = idx & 1023;
            int r = rem >> 3, c16 = rem & 7;
            const __nv_bfloat16* src = (arr ? Qlo : Qhi)
                + ((size_t)(bh * L_SEQ + q0 + r)) * HD + c16 * 8;
            cp16(sb + (arr ? FL_QLO : FL_QHI) + SWZ(r * 128 + c16 * 16), src);
        }
        CP_COMMIT();
    }

    auto issueKV = [&](int kt) {
        uint32_t buf = sb + FL_BUF + (kt & 1) * FL_BUFSZ;
        int k0 = kt * 64;
#pragma unroll
        for (int i = 0; i < 8; ++i) {
            int idx = tid + i * 256;
            int arr = idx >> 9;               // 0 Khi 1 Klo 2 Vhi 3 Vlo
            int rem = idx & 511;
            int r = rem >> 3, c16 = rem & 7;
            const __nv_bfloat16* base =
                (arr == 0) ? Khi : (arr == 1) ? Klo : (arr == 2) ? Vhi : Vlo;
            const __nv_bfloat16* src = base
                + ((size_t)(bh * L_SEQ + k0 + r)) * HD + c16 * 8;
            cp16(buf + arr * 8192 + SWZ(r * 128 + c16 * 16), src);
        }
        CP_COMMIT();
    };

    issueKV(0);
    CP_WAIT0();
    __syncthreads();

    // Q fragments (persist in registers)
    uint32_t qh[4][4], ql[4][4];
    {
        const int lr = lane & 15, lc = lane >> 4;
#pragma unroll
        for (int kc = 0; kc < 4; ++kc) {
            uint32_t o = SWZ((wq + lr) * 128 + kc * 32 + lc * 16);
            ldm_x4(qh[kc], sb + FL_QHI + o);
            ldm_x4(ql[kc], sb + FL_QLO + o);
        }
    }

    float O[8][4];
#pragma unroll
    for (int i = 0; i < 8; ++i)
#pragma unroll
        for (int j = 0; j < 4; ++j) O[i][j] = 0.f;
    float m0r = NEG_INF, m1r = NEG_INF, l0r = 0.f, l1r = 0.f;

    const int brow = (lane & 7) + ((lane >> 4) & 1) * 8;
    const int bch  = (lane >> 3) & 1;
    const int vrow = (lane & 7) + ((lane >> 3) & 1) * 8;
    const int vch  = lane >> 4;
    const int er   = lane >> 2, ec = (lane & 3) * 2;
    const int qr0  = q0 + wq + er;

    for (int kt = 0; kt < nk; ++kt) {
        if (kt + 1 < nk) issueKV(kt + 1);
        const uint32_t kb = sb + FL_BUF + (kt & 1) * FL_BUFSZ;
        const int k0 = kt * 64;

        // ---- S = (Q/8) K^T -------------------------------------------------
        float S[8][4];
#pragma unroll
        for (int i = 0; i < 8; ++i)
#pragma unroll
            for (int j = 0; j < 4; ++j) S[i][j] = 0.f;

#pragma unroll
        for (int kc = 0; kc < 4; ++kc) {
            uint32_t kh[16], kl[16];
#pragma unroll
            for (int kg = 0; kg < 4; ++kg) {
                uint32_t o = SWZ((kg * 16 + brow) * 128 + kc * 32 + bch * 16);
                ldm_x4(&kh[kg * 4], kb + o);
                ldm_x4(&kl[kg * 4], kb + 8192 + o);
            }
#pragma unroll
            for (int nt = 0; nt < 8; ++nt) {
                mma_bf16(S[nt], qh[kc], &kh[nt * 2]);
                mma_bf16(S[nt], qh[kc], &kl[nt * 2]);
                mma_bf16(S[nt], ql[kc], &kh[nt * 2]);
            }
        }

        // ---- bias + mask + online softmax ---------------------------------
        const bool msk = (kt >= 2 * qi);
        float tm0 = NEG_INF, tm1 = NEG_INF;
#pragma unroll
        for (int nt = 0; nt < 8; ++nt) {
            int kk = k0 + nt * 8 + ec;
            if (msk) {
#pragma unroll
                for (int j = 0; j < 2; ++j) {
                    int k = kk + j;
                    S[nt][j]     = (k <= qr0)     ? S[nt][j]     + LUT[qr0 - k]     : NEG_INF;
                    S[nt][j + 2] = (k <= qr0 + 8) ? S[nt][j + 2] + LUT[qr0 + 8 - k] : NEG_INF;
                }
            } else {
#pragma unroll
                for (int j = 0; j < 2; ++j) {
                    S[nt][j]     += LUT[qr0 - kk - j];
                    S[nt][j + 2] += LUT[qr0 + 8 - kk - j];
                }
            }
            tm0 = fmaxf(tm0, fmaxf(S[nt][0], S[nt][1]));
            tm1 = fmaxf(tm1, fmaxf(S[nt][2], S[nt][3]));
        }
#pragma unroll
        for (int d = 1; d < 4; d <<= 1) {
            tm0 = fmaxf(tm0, __shfl_xor_sync(0xffffffffu, tm0, d));
            tm1 = fmaxf(tm1, __shfl_xor_sync(0xffffffffu, tm1, d));
        }
        float mn0 = fmaxf(m0r, tm0), mn1 = fmaxf(m1r, tm1);
        float a0 = __expf(m0r - mn0), a1 = __expf(m1r - mn1);
        m0r = mn0; m1r = mn1;
        float ls0 = 0.f, ls1 = 0.f;
#pragma unroll
        for (int nt = 0; nt < 8; ++nt) {
            S[nt][0] = __expf(S[nt][0] - mn0); ls0 += S[nt][0];
            S[nt][1] = __expf(S[nt][1] - mn0); ls0 += S[nt][1];
            S[nt][2] = __expf(S[nt][2] - mn1); ls1 += S[nt][2];
            S[nt][3] = __expf(S[nt][3] - mn1); ls1 += S[nt][3];
        }
#pragma unroll
        for (int d = 1; d < 4; d <<= 1) {
            ls0 += __shfl_xor_sync(0xffffffffu, ls0, d);
            ls1 += __shfl_xor_sync(0xffffffffu, ls1, d);
        }
        l0r = l0r * a0 + ls0;
        l1r = l1r * a1 + ls1;
#pragma unroll
        for (int nt = 0; nt < 8; ++nt) {
            O[nt][0] *= a0; O[nt][1] *= a0;
            O[nt][2] *= a1; O[nt][3] *= a1;
        }

        // ---- O += P V  (P packed in registers, V via ldmatrix.trans) ------
#pragma unroll
        for (int kc = 0; kc < 4; ++kc) {
            const int t0 = kc * 2, t1 = kc * 2 + 1;
            uint32_t ph[4], pl[4];
            ph[0] = pack_hi(S[t0][0], S[t0][1]);
            ph[1] = pack_hi(S[t0][2], S[t0][3]);
            ph[2] = pack_hi(S[t1][0], S[t1][1]);
            ph[3] = pack_hi(S[t1][2], S[t1][3]);
            pl[0] = pack_lo(S[t0][0], S[t0][1]);
            pl[1] = pack_lo(S[t0][2], S[t0][3]);
            pl[2] = pack_lo(S[t1][0], S[t1][1]);
            pl[3] = pack_lo(S[t1][2], S[t1][3]);
#pragma unroll
            for (int dt = 0; dt < 4; ++dt) {
                uint32_t vh[4], vl[4];
                uint32_t o = SWZ((kc * 16 + vrow) * 128 + dt * 32 + vch * 16);
                ldm_x4_t(vh, kb + 16384 + o);
                ldm_x4_t(vl, kb + 24576 + o);
#pragma unroll
                for (int g = 0; g < 2; ++g) {
                    int nt = dt * 2 + g;
                    mma_bf16(O[nt], ph, &vh[g * 2]);
                    mma_bf16(O[nt], ph, &vl[g * 2]);
                    mma_bf16(O[nt], pl, &vh[g * 2]);
                }
            }
        }

        if (kt + 1 < nk) { CP_WAIT0(); __syncthreads(); }
    }

    // ---- normalize + write bf16 hi/lo in [B, L, H*64] ----------------------
    const float inv0 = 1.0f / l0r, inv1 = 1.0f / l1r;
#pragma unroll
    for (int nt = 0; nt < 8; ++nt) {
        int d = nt * 8 + ec;
        size_t i0 = ((size_t)(b * L_SEQ + qr0)     * NHEADS + h) * HD + d;
        size_t i1 = ((size_t)(b * L_SEQ + qr0 + 8) * NHEADS + h) * HD + d;
        float v00 = O[nt][0] * inv0, v01 = O[nt][1] * inv0;
        float v10 = O[nt][2] * inv1, v11 = O[nt][3] * inv1;
        *(uint32_t*)(Ohi + i0) = pack_hi(v00, v01);
        *(uint32_t*)(Olo + i0) = pack_lo(v00, v01);
        *(uint32_t*)(Ohi + i1) = pack_hi(v10, v11);
        *(uint32_t*)(Olo + i1) = pack_lo(v10, v11);
    }
}

// ===========================================================================
extern "C" void kernel_launch(void* const* d_in, const int* in_sizes, int n_in,
                              void* d_out, int out_size)
{
    const float* query = (const float*)d_in[0];
    const float* key   = (const float*)d_in[1];
    const float* value = (const float*)d_in[2];
    const float* Wq    = (const float*)d_in[5];
    const float* bq    = (const float*)d_in[6];
    const float* Wk    = (const float*)d_in[7];
    const float* bk    = (const float*)d_in[8];
    const float* Wv    = (const float*)d_in[9];
    const float* bv    = (const float*)d_in[10];
    const float* Wo    = (const float*)d_in[11];
    const float* bo    = (const float*)d_in[12];
    const float* rel   = (const float*)d_in[13];

    __nv_bfloat16 *Ih, *Il, *Wh, *Wl;
    __nv_bfloat16 *Qhi, *Qlo, *Khi, *Klo, *Vhi, *Vlo, *Ohi, *Olo;
    cudaGetSymbolAddress((void**)&Ih,  g_Ih);
    cudaGetSymbolAddress((void**)&Il,  g_Il);
    cudaGetSymbolAddress((void**)&Wh,  g_Wh);
    cudaGetSymbolAddress((void**)&Wl,  g_Wl);
    cudaGetSymbolAddress((void**)&Qhi, g_Qhi);
    cudaGetSymbolAddress((void**)&Qlo, g_Qlo);
    cudaGetSymbolAddress((void**)&Khi, g_Khi);
    cudaGetSymbolAddress((void**)&Klo, g_Klo);
    cudaGetSymbolAddress((void**)&Vhi, g_Vhi);
    cudaGetSymbolAddress((void**)&Vlo, g_Vlo);
    cudaGetSymbolAddress((void**)&Ohi, g_Ohi);
    cudaGetSymbolAddress((void**)&Olo, g_Olo);

    cudaFuncSetAttribute(tc_gemm,   cudaFuncAttributeMaxDynamicSharedMemorySize, GEMM_SMEM);
    cudaFuncSetAttribute(flash_mma, cudaFuncAttributeMaxDynamicSharedMemorySize, FLASH_SMEM);

    dim3 gb(DMODEL / 128, MROWS / 128);   // (8, 32)

    // 1) batched splits
    split_in3<<<dim3(AM / 4 / 256, 3), 256>>>((const float4*)query, (const float4*)key,
                                              (const float4*)value, (uint2*)Ih, (uint2*)Il);
    split_w4<<<dim3(WM / 4 / 256, 4), 256>>>((const float4*)Wq, (const float4*)Wk,
                                             (const float4*)Wv, (const float4*)Wo,
                                             (uint2*)Wh, (uint2*)Wl);

    // 2) projections; Q pre-scaled by 0.125
    tc_gemm<<<gb, 256, GEMM_SMEM>>>(Ih,            Il,            Wh,            Wl,
                                    bq, nullptr, Qhi, Qlo, 0.125f, 1);
    tc_gemm<<<gb, 256, GEMM_SMEM>>>(Ih + (size_t)1 * AM, Il + (size_t)1 * AM,
                                    Wh + (size_t)1 * WM, Wl + (size_t)1 * WM,
                                    bk, nullptr, Khi, Klo, 1.0f, 1);
    tc_gemm<<<gb, 256, GEMM_SMEM>>>(Ih + (size_t)2 * AM, Il + (size_t)2 * AM,
                                    Wh + (size_t)2 * WM, Wl + (size_t)2 * WM,
                                    bv, nullptr, Vhi, Vlo, 1.0f, 1);

    // 3) flash attention -> bf16 hi/lo [B,L,D]
    flash_mma<<<dim3(16, 32), 256, FLASH_SMEM>>>(Qhi, Qlo, Khi, Klo, Vhi, Vlo,
                                                 rel, Ohi, Olo);

    // 4) output projection
    tc_gemm<<<gb, 256, GEMM_SMEM>>>(Ohi, Olo,
                                    Wh + (size_t)3 * WM, Wl + (size_t)3 * WM,
                                    bo, (float*)d_out, nullptr, nullptr, 1.0f, 0);
}